// round 12
// baseline (speedup 1.0000x reference)
#include <cuda_runtime.h>
#include <cuda_fp16.h>
#include <math.h>
#include <stdint.h>

// TreeLSTM — round 12: R11 + fully-coalesced epilogue global accesses.
// cc multiply moved into the transposed phase (coalesced 128B reads);
// gate stores routed through smem transpose (coalesced 128B writes).

#define D    256
#define D3   768
#define MAX_P 100000
#define MAX_E 400000

// ---------------- scratch ----------------
__device__ float g_fc[(size_t)MAX_P * D];
__device__ float g_iact[(size_t)MAX_P * D];
__device__ float g_gact[(size_t)MAX_P * D];
__device__ __half g_hs16[(size_t)MAX_E * D];     // child_hs as fp16
__device__ __half g_hssum16[(size_t)MAX_P * D];  // hs_sum as fp16
__device__ __half g_wf16[D * D];                 // W_f^T fp16
__device__ __half g_wg16[D3 * D];                // W_gates^T fp16

// ---------------- helpers ----------------
__device__ __forceinline__ uint32_t smem_to_u32(const void* p) {
    uint32_t a;
    asm("{ .reg .u64 t; cvta.to.shared.u64 t, %1; cvt.u32.u64 %0, t; }" : "=r"(a) : "l"(p));
    return a;
}
__device__ __forceinline__ float sigmoid_f(float x) { return 1.0f / (1.0f + __expf(-x)); }

#define CP_ASYNC16(dst, src) \
    asm volatile("cp.async.cg.shared.global [%0], [%1], 16;" :: "r"(dst), "l"(src))
#define CP_COMMIT() asm volatile("cp.async.commit_group;")
#define CP_WAIT_1() asm volatile("cp.async.wait_group 1;")

__device__ __forceinline__ void ldsm_x4(uint32_t a[4], uint32_t addr) {
    asm volatile("ldmatrix.sync.aligned.m8n8.x4.shared.b16 {%0,%1,%2,%3}, [%4];"
        : "=r"(a[0]), "=r"(a[1]), "=r"(a[2]), "=r"(a[3]) : "r"(addr));
}
__device__ __forceinline__ void mma_f16(float c[4], const uint32_t a[4], const uint32_t b[2]) {
    asm volatile(
        "mma.sync.aligned.m16n8k16.row.col.f32.f16.f16.f32 "
        "{%0,%1,%2,%3}, {%4,%5,%6,%7}, {%8,%9}, {%0,%1,%2,%3};"
        : "+f"(c[0]), "+f"(c[1]), "+f"(c[2]), "+f"(c[3])
        : "r"(a[0]), "r"(a[1]), "r"(a[2]), "r"(a[3]), "r"(b[0]), "r"(b[1]));
}

// Swizzled byte offset in a [rows][64 fp16] tile: 128B rows, 8 chunks of 16B.
__device__ __forceinline__ uint32_t swz8(int row, int ch) {
    return (uint32_t)(row * 128 + (((ch) ^ ((row) & 7)) << 4));
}

// ---------------------------------------------------------------------------
// k_wsplit: W[256 x ncols] -> T [ncols][256] fp16 (transpose + round)
// ---------------------------------------------------------------------------
__global__ void k_wsplit(const float* __restrict__ W, int ncols,
                         __half* __restrict__ T) {
    __shared__ float s[32][33];
    int nt = blockIdx.x * 32, kt = blockIdx.y * 32;
    int tx = threadIdx.x & 31, ty = threadIdx.x >> 5;
    #pragma unroll
    for (int i = 0; i < 4; ++i)
        s[ty + i * 8][tx] = W[(size_t)(kt + ty + i * 8) * ncols + nt + tx];
    __syncthreads();
    #pragma unroll
    for (int i = 0; i < 4; ++i) {
        int n = nt + ty + i * 8;
        int k = kt + tx;
        T[(size_t)n * D + k] = __float2half_rn(s[tx][ty + i * 8]);
    }
}

// ---------------------------------------------------------------------------
// k_hs_sum: segment sum of child_hs -> fp16 hs_sum; also child_hs -> fp16
// ---------------------------------------------------------------------------
__global__ void k_hs_sum(const float* __restrict__ hs, const int* __restrict__ seg,
                         int E, __half* __restrict__ hs16,
                         __half* __restrict__ sum16) {
    __shared__ int sb2[2];
    int p = blockIdx.x;
    if (threadIdx.x < 2) {
        int target = p + (int)threadIdx.x;
        int lo = 0, hi = E;
        while (lo < hi) { int m = (lo + hi) >> 1; if (seg[m] < target) lo = m + 1; else hi = m; }
        sb2[threadIdx.x] = lo;
    }
    __syncthreads();
    int lo = sb2[0], hi = sb2[1];
    float s = 0.0f;
    for (int e = lo; e < hi; ++e) {
        float v = hs[(size_t)e * D + threadIdx.x];
        s += v;
        hs16[(size_t)e * D + threadIdx.x] = __float2half_rn(v);
    }
    sum16[(size_t)p * D + threadIdx.x] = __float2half_rn(s);
}

// ---------------------------------------------------------------------------
// k_gemm<MODE>: single-pass fp16 GEMM. CTA 128x128, 256 thr, 8 warps (2m x 4n),
// warp tile 64x32, BK=64, 4 chunks, 3-stage cp.async, 2 CTAs/SM.
// blockIdx.x: MODE0 -> nhalf (0..1); MODE1 -> gate*2 + nhalf (0..5).
// Epilogue (both modes): fragment->smem transpose; all global accesses in the
// transposed phase are warp-coalesced 128B lines.
// MODE 0: run-merged atomicAdd of sigmoid(v)*cc into fc.
// MODE 1: coalesced activation stores.
// ---------------------------------------------------------------------------
#define SM_A    0            // 128 rows x 64 fp16 = 16384
#define SM_B    16384
#define SM_STAGE 32768
#define SM_SEGS (3 * SM_STAGE)          // 128 ints
#define SM_TOTAL (3 * SM_STAGE + 512)
// epilogue fp32 buffers overlay the stage area: 4 slices x 128 x 33 fp32
#define BUF_STRIDE 33
#define BUF_BYTES (128 * BUF_STRIDE * 4)   // 16896

template <int MODE>
__global__ void __launch_bounds__(256, 2)
k_gemm(const __half* __restrict__ A16,
       const __half* __restrict__ Bt_g,
       const float* __restrict__ bias_g,
       const float* __restrict__ cc,
       const int* __restrict__ seg,
       float* __restrict__ fc,
       float* __restrict__ o0, float* __restrict__ o1, float* __restrict__ o2,
       int Mtot) {
    extern __shared__ char smem[];
    const uint32_t sb = smem_to_u32(smem);
    const int tid  = threadIdx.x;
    const int lane = tid & 31;
    const int wid  = tid >> 5;
    const int wm   = wid >> 2;          // 0..1
    const int wn   = wid & 3;           // 0..3
    const int bm   = blockIdx.y * 128;
    const int gate  = (MODE == 1) ? ((int)blockIdx.x >> 1) : 0;
    const int nhalf = (MODE == 1) ? ((int)blockIdx.x & 1) : (int)blockIdx.x;

    const __half* Bt = Bt_g + ((size_t)gate * 256 + nhalf * 128) * D;
    const float* bias = bias_g + gate * 256 + nhalf * 128;

    // MODE 0: stash segment ids for this row tile
    int* ssegs = (int*)(smem + SM_SEGS);
    if (MODE == 0 && tid < 128) {
        int r = bm + tid;
        ssegs[tid] = (r < Mtot) ? seg[r] : -1;
    }

    float acc[4][4][4];
    #pragma unroll
    for (int i = 0; i < 4; ++i)
        #pragma unroll
        for (int j = 0; j < 4; ++j)
            #pragma unroll
            for (int q = 0; q < 4; ++q) acc[i][j][q] = 0.f;

#define STAGE(kc, slot) do { \
        _Pragma("unroll") \
        for (int _it = 0; _it < 4; ++_it) { \
            int _u = tid + _it * 256; int _r = _u >> 3; int _c = _u & 7; \
            int _ar = min(bm + _r, Mtot - 1); \
            uint32_t _o = swz8(_r, _c); \
            CP_ASYNC16(sb + (slot) + SM_A + _o, \
                       A16 + (size_t)_ar * D + (kc) * 64 + _c * 8); \
            CP_ASYNC16(sb + (slot) + SM_B + _o, \
                       Bt + (size_t)_r * D + (kc) * 64 + _c * 8); \
        } \
    } while (0)

    STAGE(0, 0);
    CP_COMMIT();
    STAGE(1, SM_STAGE);
    CP_COMMIT();

    const int l7  = lane & 7;
    const int l8  = (lane >> 3) & 1;
    const int l16 = lane >> 4;
    const int arow_f = wm * 64 + l8 * 8 + l7;                      // + mf*16
    const int brow   = wn * 32 + (lane & 7) + ((lane >> 4) << 3);  // + nb*16
    const int bch    = (lane >> 3) & 1;

    #pragma unroll 1
    for (int kc = 0; kc < 4; ++kc) {
        CP_WAIT_1();
        __syncthreads();
        if (kc + 2 < 4) {
            uint32_t ns = (uint32_t)(((kc + 2) % 3) * SM_STAGE);
            STAGE(kc + 2, ns);
        }
        CP_COMMIT();

        const uint32_t base = sb + (uint32_t)((kc % 3) * SM_STAGE);
        uint32_t ah[4][4], bb[2][4];
        #pragma unroll
        for (int s = 0; s < 4; ++s) {
            #pragma unroll
            for (int mf = 0; mf < 4; ++mf)
                ldsm_x4(ah[mf], base + SM_A + swz8(arow_f + mf * 16, 2 * s + l16));
            #pragma unroll
            for (int nb = 0; nb < 2; ++nb)
                ldsm_x4(bb[nb], base + SM_B + swz8(brow + nb * 16, 2 * s + bch));
            #pragma unroll
            for (int mf = 0; mf < 4; ++mf)
                #pragma unroll
                for (int nf = 0; nf < 4; ++nf)
                    mma_f16(acc[mf][nf], ah[mf], &bb[nf >> 1][(nf & 1) * 2]);
        }
    }

    // ---- epilogue ----
    float2 bias2[4];
    #pragma unroll
    for (int nf = 0; nf < 4; ++nf)
        bias2[nf] = *(const float2*)(bias + wn * 32 + nf * 8 + 2 * (lane & 3));

    // Phase 1: fragments -> activation -> smem slice buffer (register-only).
    __syncthreads();   // all warps done reading stage smem
    {
        float* buf = (float*)(smem + wn * BUF_BYTES);   // this warp's n-slice
        #pragma unroll
        for (int mf = 0; mf < 4; ++mf) {
            #pragma unroll
            for (int half = 0; half < 2; ++half) {
                int rl = wm * 64 + mf * 16 + (lane >> 2) + half * 8;  // 0..127
                #pragma unroll
                for (int nf = 0; nf < 4; ++nf) {
                    int cl = nf * 8 + 2 * (lane & 3);                 // 0..31
                    float v0 = acc[mf][nf][half * 2 + 0] + bias2[nf].x;
                    float v1 = acc[mf][nf][half * 2 + 1] + bias2[nf].y;
                    float r0, r1;
                    if (MODE == 1 && gate == 2) { r0 = tanhf(v0); r1 = tanhf(v1); }
                    else                        { r0 = sigmoid_f(v0); r1 = sigmoid_f(v1); }
                    buf[rl * BUF_STRIDE + cl]     = r0;
                    buf[rl * BUF_STRIDE + cl + 1] = r1;
                }
            }
        }
    }
    __syncthreads();

    // Phase 2: transposed, fully coalesced global phase.
    int col = tid & 31;
    int grp = tid >> 5;
    if (MODE == 0) {
        // run-merge by sorted sid; cc read here (coalesced), then atomics.
        #pragma unroll 1
        for (int ns = 0; ns < 4; ++ns) {
            const float* b2 = (const float*)(smem + ns * BUF_BYTES);
            int cn = nhalf * 128 + ns * 32 + col;
            int cur = ssegs[grp * 16];
            float run = 0.f;
            #pragma unroll
            for (int i = 0; i < 16; ++i) {
                int rl = grp * 16 + i;
                int sid = ssegs[rl];
                if (sid != cur) {
                    if (cur >= 0) atomicAdd(fc + (size_t)cur * D + cn, run);
                    cur = sid;
                    run = 0.f;
                }
                if (sid >= 0)
                    run += b2[rl * BUF_STRIDE + col] *
                           cc[(size_t)(bm + rl) * D + cn];
            }
            if (cur >= 0) atomicAdd(fc + (size_t)cur * D + cn, run);
        }
    } else {
        float* op = (gate == 0) ? o0 : (gate == 1) ? o1 : o2;
        #pragma unroll 1
        for (int ns = 0; ns < 4; ++ns) {
            const float* b2 = (const float*)(smem + ns * BUF_BYTES);
            int cn = nhalf * 128 + ns * 32 + col;
            #pragma unroll
            for (int i = 0; i < 16; ++i) {
                int rl = grp * 16 + i;
                int r = bm + rl;
                if (r < Mtot)
                    op[(size_t)r * D + cn] = b2[rl * BUF_STRIDE + col];
            }
        }
    }
#undef STAGE
}

// ---------------------------------------------------------------------------
// k_final: c = i*g + fc; h = o*tanh(c)
// ---------------------------------------------------------------------------
__global__ void k_final(const float* __restrict__ fc, const float* __restrict__ gi,
                        const float* __restrict__ gg, float* __restrict__ out,
                        int total) {
    int i4 = blockIdx.x * blockDim.x + threadIdx.x;
    if (i4 * 4 < total) {
        size_t idx = (size_t)i4 * 4;
        float4 vi = *(const float4*)(gi + idx);
        float4 vg = *(const float4*)(gg + idx);
        float4 vf = *(const float4*)(fc + idx);
        float4 vo = *(const float4*)(out + idx);
        float4 c = make_float4(vi.x * vg.x + vf.x, vi.y * vg.y + vf.y,
                               vi.z * vg.z + vf.z, vi.w * vg.w + vf.w);
        float4 h = make_float4(vo.x * tanhf(c.x), vo.y * tanhf(c.y),
                               vo.z * tanhf(c.z), vo.w * tanhf(c.w));
        *(float4*)(out + (size_t)total + idx) = c;
        *(float4*)(out + idx) = h;
    }
}

// ---------------------------------------------------------------------------
extern "C" void kernel_launch(void* const* d_in, const int* in_sizes, int n_in,
                              void* d_out, int out_size) {
    const float* child_hs = (const float*)d_in[0];
    const float* child_cs = (const float*)d_in[1];
    const int*   seg      = (const int*)d_in[2];
    const float* Wg = (const float*)d_in[4];
    const float* bg = (const float*)d_in[5];
    const float* Wf = (const float*)d_in[6];
    const float* bf = (const float*)d_in[7];
    (void)n_in;

    int E = in_sizes[2];
    int P = out_size / (2 * D);
    if (P > MAX_P) P = MAX_P;
    if (E > MAX_E) E = MAX_E;

    float* out = (float*)d_out;

    static bool inited = false;
    static float *fc_p, *ia_p, *ga_p;
    static __half *hs16_p, *sum16_p, *wf_p, *wg_p;
    if (!inited) {
        cudaGetSymbolAddress((void**)&fc_p,    g_fc);
        cudaGetSymbolAddress((void**)&ia_p,    g_iact);
        cudaGetSymbolAddress((void**)&ga_p,    g_gact);
        cudaGetSymbolAddress((void**)&hs16_p,  g_hs16);
        cudaGetSymbolAddress((void**)&sum16_p, g_hssum16);
        cudaGetSymbolAddress((void**)&wf_p,    g_wf16);
        cudaGetSymbolAddress((void**)&wg_p,    g_wg16);
        cudaFuncSetAttribute(k_gemm<0>, cudaFuncAttributeMaxDynamicSharedMemorySize, SM_TOTAL);
        cudaFuncSetAttribute(k_gemm<1>, cudaFuncAttributeMaxDynamicSharedMemorySize, SM_TOTAL);
        inited = true;
    }

    // weight transpose + fp16 round
    k_wsplit<<<dim3(D / 32, D / 32), 256>>>(Wf, D, wf_p);
    k_wsplit<<<dim3(D3 / 32, D / 32), 256>>>(Wg, D3, wg_p);

    // zero fc accumulator
    cudaMemsetAsync(fc_p, 0, (size_t)P * D * sizeof(float), 0);

    // segment sum (emits fp16 hs_sum) + child_hs -> fp16
    k_hs_sum<<<P, 256>>>(child_hs, seg, E, hs16_p, sum16_p);

    // fGEMM: fc[seg[e]] += sigmoid(hs@Wf^T + bf) * cs  (coalesced epilogue)
    k_gemm<0><<<dim3(2, (E + 127) / 128), 256, SM_TOTAL>>>(
        hs16_p, wf_p, bf, child_cs, seg, fc_p,
        nullptr, nullptr, nullptr, E);

    // gates GEMM: gate 0 -> sig(i), 1 -> sig(o) into out_h, 2 -> tanh(g)
    k_gemm<1><<<dim3(6, (P + 127) / 128), 256, SM_TOTAL>>>(
        sum16_p, wg_p, bg, nullptr, nullptr, nullptr,
        ia_p, out, ga_p, P);

    // final elementwise combine
    k_final<<<(P * D / 4 + 255) / 256, 256>>>(fc_p, ia_p, ga_p, out, P * D);
}

// round 13
// speedup vs baseline: 1.4830x; 1.4830x over previous
#include <cuda_runtime.h>
#include <cuda_fp16.h>
#include <math.h>
#include <stdint.h>

// TreeLSTM — round 13: single-pass fp16 HMMA, CTA 64x128 (256 thr, 8 warps
// 2m x 4n, warp tile 32x32), BK=64, 3-stage cp.async, ~80 regs -> 3 CTAs/SM
// (24 warps). Attacks the latency-bound plateau by raising occupancy.

#define D    256
#define D3   768
#define MAX_P 100000
#define MAX_E 400000

// ---------------- scratch ----------------
__device__ float g_fc[(size_t)MAX_P * D];
__device__ float g_iact[(size_t)MAX_P * D];
__device__ float g_gact[(size_t)MAX_P * D];
__device__ __half g_hs16[(size_t)MAX_E * D];     // child_hs as fp16
__device__ __half g_hssum16[(size_t)MAX_P * D];  // hs_sum as fp16
__device__ __half g_wf16[D * D];                 // W_f^T fp16
__device__ __half g_wg16[D3 * D];                // W_gates^T fp16

// ---------------- helpers ----------------
__device__ __forceinline__ uint32_t smem_to_u32(const void* p) {
    uint32_t a;
    asm("{ .reg .u64 t; cvta.to.shared.u64 t, %1; cvt.u32.u64 %0, t; }" : "=r"(a) : "l"(p));
    return a;
}
__device__ __forceinline__ float sigmoid_f(float x) { return 1.0f / (1.0f + __expf(-x)); }

#define CP_ASYNC16(dst, src) \
    asm volatile("cp.async.cg.shared.global [%0], [%1], 16;" :: "r"(dst), "l"(src))
#define CP_COMMIT() asm volatile("cp.async.commit_group;")
#define CP_WAIT_1() asm volatile("cp.async.wait_group 1;")

__device__ __forceinline__ void ldsm_x4(uint32_t a[4], uint32_t addr) {
    asm volatile("ldmatrix.sync.aligned.m8n8.x4.shared.b16 {%0,%1,%2,%3}, [%4];"
        : "=r"(a[0]), "=r"(a[1]), "=r"(a[2]), "=r"(a[3]) : "r"(addr));
}
__device__ __forceinline__ void mma_f16(float c[4], const uint32_t a[4], const uint32_t b[2]) {
    asm volatile(
        "mma.sync.aligned.m16n8k16.row.col.f32.f16.f16.f32 "
        "{%0,%1,%2,%3}, {%4,%5,%6,%7}, {%8,%9}, {%0,%1,%2,%3};"
        : "+f"(c[0]), "+f"(c[1]), "+f"(c[2]), "+f"(c[3])
        : "r"(a[0]), "r"(a[1]), "r"(a[2]), "r"(a[3]), "r"(b[0]), "r"(b[1]));
}

// Swizzled byte offset in a [rows][64 fp16] tile: 128B rows, 8 chunks of 16B.
__device__ __forceinline__ uint32_t swz8(int row, int ch) {
    return (uint32_t)(row * 128 + (((ch) ^ ((row) & 7)) << 4));
}

// ---------------------------------------------------------------------------
// k_wsplit: W[256 x ncols] -> T [ncols][256] fp16 (transpose + round)
// ---------------------------------------------------------------------------
__global__ void k_wsplit(const float* __restrict__ W, int ncols,
                         __half* __restrict__ T) {
    __shared__ float s[32][33];
    int nt = blockIdx.x * 32, kt = blockIdx.y * 32;
    int tx = threadIdx.x & 31, ty = threadIdx.x >> 5;
    #pragma unroll
    for (int i = 0; i < 4; ++i)
        s[ty + i * 8][tx] = W[(size_t)(kt + ty + i * 8) * ncols + nt + tx];
    __syncthreads();
    #pragma unroll
    for (int i = 0; i < 4; ++i) {
        int n = nt + ty + i * 8;
        int k = kt + tx;
        T[(size_t)n * D + k] = __float2half_rn(s[tx][ty + i * 8]);
    }
}

// ---------------------------------------------------------------------------
// k_hs_sum: segment sum of child_hs -> fp16 hs_sum; also child_hs -> fp16
// ---------------------------------------------------------------------------
__global__ void k_hs_sum(const float* __restrict__ hs, const int* __restrict__ seg,
                         int E, __half* __restrict__ hs16,
                         __half* __restrict__ sum16) {
    __shared__ int sb2[2];
    int p = blockIdx.x;
    if (threadIdx.x < 2) {
        int target = p + (int)threadIdx.x;
        int lo = 0, hi = E;
        while (lo < hi) { int m = (lo + hi) >> 1; if (seg[m] < target) lo = m + 1; else hi = m; }
        sb2[threadIdx.x] = lo;
    }
    __syncthreads();
    int lo = sb2[0], hi = sb2[1];
    float s = 0.0f;
    for (int e = lo; e < hi; ++e) {
        float v = hs[(size_t)e * D + threadIdx.x];
        s += v;
        hs16[(size_t)e * D + threadIdx.x] = __float2half_rn(v);
    }
    sum16[(size_t)p * D + threadIdx.x] = __float2half_rn(s);
}

// ---------------------------------------------------------------------------
// k_gemm<MODE>: single-pass fp16 GEMM. CTA 64x128, 256 thr, 8 warps (2m x 4n),
// warp tile 32x32, BK=64, 4 chunks, 3-stage cp.async, 3 CTAs/SM.
// blockIdx.x: MODE0 -> nhalf (0..1); MODE1 -> gate*2 + nhalf (0..5).
// MODE 0: atomicAdd fc[seg[row]] += sigmoid(v + b) * cc[row].
// MODE 1: per-gate activation stores (sig/sig/tanh).
// ---------------------------------------------------------------------------
#define SM_A    0            // 64 rows x 64 fp16  = 8192
#define SM_B    8192         // 128 rows x 64 fp16 = 16384
#define SM_STAGE 24576
#define SM_TOTAL (3 * SM_STAGE + 512)

template <int MODE>
__global__ void __launch_bounds__(256, 3)
k_gemm(const __half* __restrict__ A16,
       const __half* __restrict__ Bt_g,
       const float* __restrict__ bias_g,
       const float* __restrict__ cc,
       const int* __restrict__ seg,
       float* __restrict__ fc,
       float* __restrict__ o0, float* __restrict__ o1, float* __restrict__ o2,
       int Mtot) {
    extern __shared__ char smem[];
    const uint32_t sb = smem_to_u32(smem);
    const int tid  = threadIdx.x;
    const int lane = tid & 31;
    const int wid  = tid >> 5;
    const int wm   = wid >> 2;          // 0..1 (32 rows each)
    const int wn   = wid & 3;           // 0..3 (32 cols each)
    const int bm   = blockIdx.y * 64;
    const int gate  = (MODE == 1) ? ((int)blockIdx.x >> 1) : 0;
    const int nhalf = (MODE == 1) ? ((int)blockIdx.x & 1) : (int)blockIdx.x;

    const __half* Bt = Bt_g + ((size_t)gate * 256 + nhalf * 128) * D;
    const float* bias = bias_g + gate * 256 + nhalf * 128;

    float acc[2][4][4];
    #pragma unroll
    for (int i = 0; i < 2; ++i)
        #pragma unroll
        for (int j = 0; j < 4; ++j)
            #pragma unroll
            for (int q = 0; q < 4; ++q) acc[i][j][q] = 0.f;

    // staging per chunk: A 64 rows x 8 units(16B) = 512 -> 2/thread;
    //                    B 128 rows x 8 units    = 1024 -> 4/thread
#define STAGE(kc, slot) do { \
        _Pragma("unroll") \
        for (int _it = 0; _it < 2; ++_it) { \
            int _u = tid + _it * 256; int _r = _u >> 3; int _c = _u & 7; \
            int _ar = min(bm + _r, Mtot - 1); \
            CP_ASYNC16(sb + (slot) + SM_A + swz8(_r, _c), \
                       A16 + (size_t)_ar * D + (kc) * 64 + _c * 8); \
        } \
        _Pragma("unroll") \
        for (int _it = 0; _it < 4; ++_it) { \
            int _u = tid + _it * 256; int _r = _u >> 3; int _c = _u & 7; \
            CP_ASYNC16(sb + (slot) + SM_B + swz8(_r, _c), \
                       Bt + (size_t)_r * D + (kc) * 64 + _c * 8); \
        } \
    } while (0)

    STAGE(0, 0);
    CP_COMMIT();
    STAGE(1, SM_STAGE);
    CP_COMMIT();

    const int l7  = lane & 7;
    const int l8  = (lane >> 3) & 1;
    const int l16 = lane >> 4;
    const int arow_f = wm * 32 + l8 * 8 + l7;                      // + mf*16
    const int brow   = wn * 32 + (lane & 7) + ((lane >> 4) << 3);  // + nb*16
    const int bch    = (lane >> 3) & 1;

    #pragma unroll 1
    for (int kc = 0; kc < 4; ++kc) {
        CP_WAIT_1();
        __syncthreads();
        if (kc + 2 < 4) {
            uint32_t ns = (uint32_t)(((kc + 2) % 3) * SM_STAGE);
            STAGE(kc + 2, ns);
        }
        CP_COMMIT();

        const uint32_t base = sb + (uint32_t)((kc % 3) * SM_STAGE);
        uint32_t ah[2][4], bb[2][4];
        #pragma unroll
        for (int s = 0; s < 4; ++s) {       // 4 k16 groups in BK=64
            #pragma unroll
            for (int mf = 0; mf < 2; ++mf)
                ldsm_x4(ah[mf], base + SM_A + swz8(arow_f + mf * 16, 2 * s + l16));
            #pragma unroll
            for (int nb = 0; nb < 2; ++nb)
                ldsm_x4(bb[nb], base + SM_B + swz8(brow + nb * 16, 2 * s + bch));
            #pragma unroll
            for (int mf = 0; mf < 2; ++mf)
                #pragma unroll
                for (int nf = 0; nf < 4; ++nf)
                    mma_f16(acc[mf][nf], ah[mf], &bb[nf >> 1][(nf & 1) * 2]);
        }
    }

    // epilogue (R10-style: direct, latency-parallel global accesses)
    float2 bias2[4];
    #pragma unroll
    for (int nf = 0; nf < 4; ++nf)
        bias2[nf] = *(const float2*)(bias + wn * 32 + nf * 8 + 2 * (lane & 3));

    #pragma unroll
    for (int mf = 0; mf < 2; ++mf) {
        #pragma unroll
        for (int half = 0; half < 2; ++half) {
            int r = bm + wm * 32 + mf * 16 + (lane >> 2) + half * 8;
            bool ok = r < Mtot;
            int sid = (MODE == 0 && ok) ? seg[r] : 0;
            #pragma unroll
            for (int nf = 0; nf < 4; ++nf) {
                int cn = nhalf * 128 + wn * 32 + nf * 8 + 2 * (lane & 3);
                float v0 = acc[mf][nf][half * 2 + 0] + bias2[nf].x;
                float v1 = acc[mf][nf][half * 2 + 1] + bias2[nf].y;
                if (!ok) continue;
                size_t o = (size_t)r * D + cn;
                if (MODE == 0) {
                    float2 ccv = *(const float2*)(cc + o);
                    float* dst = fc + (size_t)sid * D + cn;
                    atomicAdd(dst,     sigmoid_f(v0) * ccv.x);
                    atomicAdd(dst + 1, sigmoid_f(v1) * ccv.y);
                } else {
                    float r0, r1;
                    if (gate == 2) { r0 = tanhf(v0); r1 = tanhf(v1); }
                    else           { r0 = sigmoid_f(v0); r1 = sigmoid_f(v1); }
                    float* op = (gate == 0) ? o0 : (gate == 1) ? o1 : o2;
                    *(float2*)(op + o) = make_float2(r0, r1);
                }
            }
        }
    }
#undef STAGE
}

// ---------------------------------------------------------------------------
// k_final: c = i*g + fc; h = o*tanh(c)
// ---------------------------------------------------------------------------
__global__ void k_final(const float* __restrict__ fc, const float* __restrict__ gi,
                        const float* __restrict__ gg, float* __restrict__ out,
                        int total) {
    int i4 = blockIdx.x * blockDim.x + threadIdx.x;
    if (i4 * 4 < total) {
        size_t idx = (size_t)i4 * 4;
        float4 vi = *(const float4*)(gi + idx);
        float4 vg = *(const float4*)(gg + idx);
        float4 vf = *(const float4*)(fc + idx);
        float4 vo = *(const float4*)(out + idx);
        float4 c = make_float4(vi.x * vg.x + vf.x, vi.y * vg.y + vf.y,
                               vi.z * vg.z + vf.z, vi.w * vg.w + vf.w);
        float4 h = make_float4(vo.x * tanhf(c.x), vo.y * tanhf(c.y),
                               vo.z * tanhf(c.z), vo.w * tanhf(c.w));
        *(float4*)(out + (size_t)total + idx) = c;
        *(float4*)(out + idx) = h;
    }
}

// ---------------------------------------------------------------------------
extern "C" void kernel_launch(void* const* d_in, const int* in_sizes, int n_in,
                              void* d_out, int out_size) {
    const float* child_hs = (const float*)d_in[0];
    const float* child_cs = (const float*)d_in[1];
    const int*   seg      = (const int*)d_in[2];
    const float* Wg = (const float*)d_in[4];
    const float* bg = (const float*)d_in[5];
    const float* Wf = (const float*)d_in[6];
    const float* bf = (const float*)d_in[7];
    (void)n_in;

    int E = in_sizes[2];
    int P = out_size / (2 * D);
    if (P > MAX_P) P = MAX_P;
    if (E > MAX_E) E = MAX_E;

    float* out = (float*)d_out;

    static bool inited = false;
    static float *fc_p, *ia_p, *ga_p;
    static __half *hs16_p, *sum16_p, *wf_p, *wg_p;
    if (!inited) {
        cudaGetSymbolAddress((void**)&fc_p,    g_fc);
        cudaGetSymbolAddress((void**)&ia_p,    g_iact);
        cudaGetSymbolAddress((void**)&ga_p,    g_gact);
        cudaGetSymbolAddress((void**)&hs16_p,  g_hs16);
        cudaGetSymbolAddress((void**)&sum16_p, g_hssum16);
        cudaGetSymbolAddress((void**)&wf_p,    g_wf16);
        cudaGetSymbolAddress((void**)&wg_p,    g_wg16);
        cudaFuncSetAttribute(k_gemm<0>, cudaFuncAttributeMaxDynamicSharedMemorySize, SM_TOTAL);
        cudaFuncSetAttribute(k_gemm<1>, cudaFuncAttributeMaxDynamicSharedMemorySize, SM_TOTAL);
        inited = true;
    }

    // weight transpose + fp16 round
    k_wsplit<<<dim3(D / 32, D / 32), 256>>>(Wf, D, wf_p);
    k_wsplit<<<dim3(D3 / 32, D / 32), 256>>>(Wg, D3, wg_p);

    // zero fc accumulator
    cudaMemsetAsync(fc_p, 0, (size_t)P * D * sizeof(float), 0);

    // segment sum (emits fp16 hs_sum) + child_hs -> fp16
    k_hs_sum<<<P, 256>>>(child_hs, seg, E, hs16_p, sum16_p);

    // fGEMM: fc[seg[e]] += sigmoid(hs@Wf^T + bf) * cs
    k_gemm<0><<<dim3(2, (E + 63) / 64), 256, SM_TOTAL>>>(
        hs16_p, wf_p, bf, child_cs, seg, fc_p,
        nullptr, nullptr, nullptr, E);

    // gates GEMM: gate 0 -> sig(i), 1 -> sig(o) into out_h, 2 -> tanh(g)
    k_gemm<1><<<dim3(6, (P + 63) / 64), 256, SM_TOTAL>>>(
        sum16_p, wg_p, bg, nullptr, nullptr, nullptr,
        ia_p, out, ga_p, P);

    // final elementwise combine
    k_final<<<(P * D / 4 + 255) / 256, 256>>>(fc_p, ia_p, ga_p, out, P * D);
}